// round 14
// baseline (speedup 1.0000x reference)
#include <cuda_runtime.h>
#include <math.h>

// Self-convolution via real-packed shared-memory FFT: radix-8 fused passes,
// NT=512, packed f32x2 everywhere, scoped sync, zero-pad-aware pass1
// (gmem->regs), reduced middle, hoisted smem index arrays, and ALL pass
// twiddles (w1,w2,w4 per pass family) generated up-front by independent
// __sincosf calls (MUFU) instead of serial complex-squaring chains.

#define SEQ_L   4096
#define OUT_L   (2 * SEQ_L - 1)     // 8191
#define FFT_M   4096
#define NT      512

#define IDX(a)  ((a) + (((a) >> 4) << 1))       // pad 2 slots per 16
#define RE_SZ   (FFT_M + ((FFT_M >> 4) << 1))   // 4608 complex slots (36 KB)
#define S8      0.70710678118654752440f
#define C16     0.92387953251128675613f
#define S16     0.38268343236508977173f
#define W_ANG   (-6.28318530717958647692f / (float)FFT_M)

#define BAR_PAIR(tid) asm volatile("bar.sync %0, 64;" :: "r"(1 + ((tid) >> 6)) : "memory")

typedef unsigned long long q64;   // packed (float lo, float hi) complex

// ---------- packed f32x2 primitives ----------
__device__ __forceinline__ q64 qpk(float x, float y) {
    q64 r; asm("mov.b64 %0,{%1,%2};" : "=l"(r) : "f"(x), "f"(y)); return r;
}
__device__ __forceinline__ float2 qun(q64 a) {
    float2 f; asm("mov.b64 {%0,%1},%2;" : "=f"(f.x), "=f"(f.y) : "l"(a)); return f;
}
__device__ __forceinline__ q64 qswp(q64 a) {
    q64 r;
    asm("{\n\t.reg .b32 lo,hi;\n\tmov.b64 {lo,hi},%1;\n\tmov.b64 %0,{hi,lo};\n\t}"
        : "=l"(r) : "l"(a));
    return r;
}
__device__ __forceinline__ q64 qadd(q64 a, q64 b) {
    q64 r; asm("add.rn.f32x2 %0,%1,%2;" : "=l"(r) : "l"(a), "l"(b)); return r;
}
__device__ __forceinline__ q64 qmul(q64 a, q64 b) {
    q64 r; asm("mul.rn.f32x2 %0,%1,%2;" : "=l"(r) : "l"(a), "l"(b)); return r;
}
__device__ __forceinline__ q64 qfma(q64 a, q64 b, q64 c) {
    q64 r; asm("fma.rn.f32x2 %0,%1,%2,%3;" : "=l"(r) : "l"(a), "l"(b), "l"(c)); return r;
}
__device__ __forceinline__ q64 qsub(q64 a, q64 b, q64 n1) { return qfma(b, n1, a); }

struct qtw { q64 xx, sy; };
__device__ __forceinline__ qtw mk(float p, float q) {
    qtw t; t.xx = qpk(p, p); t.sy = qpk(-q, q); return t;
}
__device__ __forceinline__ q64 qcmul(q64 a, qtw t) {
    return qfma(qswp(a), t.sy, qmul(a, t.xx));
}

// ---------- scalar complex helpers ----------
__device__ __forceinline__ float2 cmul(float2 a, float2 w) {
    return make_float2(a.x * w.x - a.y * w.y, a.x * w.y + a.y * w.x);
}
__device__ __forceinline__ float2 cadd(float2 a, float2 b) {
    return make_float2(a.x + b.x, a.y + b.y);
}
__device__ __forceinline__ float2 csq(float2 a) {
    return make_float2(a.x * a.x - a.y * a.y, 2.0f * a.x * a.y);
}
__device__ __forceinline__ float2 twof(int t) {   // exp(i * W_ANG * t)
    float2 w;
    __sincosf(W_ANG * (float)t, &w.y, &w.x);
    return w;
}

extern __shared__ q64 s_z[];

// ---------- packed radix-8 (general twiddles) ----------
__device__ __forceinline__ void qfwd8_s23(q64 v[8], float2 w2, float2 w4, q64 n1) {
    const qtw T2  = mk(w2.x, w2.y);
    const qtw T2N = mk(w2.y, -w2.x);
    #pragma unroll
    for (int h = 0; h < 8; h += 4) {
        q64 u = qsub(v[h + 0], v[h + 2], n1);
        v[h + 0] = qadd(v[h + 0], v[h + 2]);
        v[h + 2] = qcmul(u, T2);
        u = qsub(v[h + 1], v[h + 3], n1);
        v[h + 1] = qadd(v[h + 1], v[h + 3]);
        v[h + 3] = qcmul(u, T2N);
    }
    const qtw T4 = mk(w4.x, w4.y);
    #pragma unroll
    for (int h = 0; h < 8; h += 2) {
        const q64 u = qsub(v[h], v[h + 1], n1);
        v[h] = qadd(v[h], v[h + 1]);
        v[h + 1] = qcmul(u, T4);
    }
}

__device__ __forceinline__ void qfwd8(q64 v[8], float2 w1, float2 w2, float2 w4, q64 n1) {
    const qtw T1 = mk(w1.x, w1.y);
    const qtw TB = mk(S8 * (w1.x + w1.y), S8 * (w1.y - w1.x));
    const qtw TC = mk(w1.y, -w1.x);
    const qtw TD = mk(-S8 * (w1.x - w1.y), -S8 * (w1.y + w1.x));

    q64 d0 = qsub(v[0], v[4], n1), d1 = qsub(v[1], v[5], n1);
    q64 d2 = qsub(v[2], v[6], n1), d3 = qsub(v[3], v[7], n1);
    v[0] = qadd(v[0], v[4]);
    v[1] = qadd(v[1], v[5]);
    v[2] = qadd(v[2], v[6]);
    v[3] = qadd(v[3], v[7]);
    v[4] = qcmul(d0, T1);
    v[5] = qcmul(d1, TB);
    v[6] = qcmul(d2, TC);
    v[7] = qcmul(d3, TD);

    qfwd8_s23(v, w2, w4, n1);
}

__device__ __forceinline__ void qinv8(q64 v[8], float2 w1, float2 w2, float2 w4, q64 n1) {
    const qtw T4C = mk(w4.x, -w4.y);
    #pragma unroll
    for (int h = 0; h < 8; h += 2) {
        const q64 t = qcmul(v[h + 1], T4C);
        v[h + 1] = qsub(v[h], t, n1);
        v[h]     = qadd(v[h], t);
    }
    const qtw T2C = mk(w2.x, -w2.y);
    const qtw T2I = mk(w2.y, w2.x);
    #pragma unroll
    for (int h = 0; h < 8; h += 4) {
        q64 t = qcmul(v[h + 2], T2C);
        v[h + 2] = qsub(v[h], t, n1);
        v[h]     = qadd(v[h], t);
        t = qcmul(v[h + 3], T2I);
        v[h + 3] = qsub(v[h + 1], t, n1);
        v[h + 1] = qadd(v[h + 1], t);
    }
    {
        const qtw T1C = mk(w1.x, -w1.y);
        const qtw TC1 = mk(S8 * (w1.x + w1.y), S8 * (w1.x - w1.y));
        const qtw TC2 = mk(w1.y, w1.x);
        const qtw TC3 = mk(-S8 * (w1.x - w1.y), S8 * (w1.y + w1.x));

        q64 t = qcmul(v[4], T1C);
        v[4] = qsub(v[0], t, n1);
        v[0] = qadd(v[0], t);
        t = qcmul(v[5], TC1);
        v[5] = qsub(v[1], t, n1);
        v[1] = qadd(v[1], t);
        t = qcmul(v[6], TC2);
        v[6] = qsub(v[2], t, n1);
        v[2] = qadd(v[2], t);
        t = qcmul(v[7], TC3);
        v[7] = qsub(v[3], t, n1);
        v[3] = qadd(v[3], t);
    }
}

// ---------- packed radix-8, UNIT twiddles (center) ----------
__device__ __forceinline__ void ufwd8(q64 v[8], q64 n1, q64 p1m1) {
    const qtw TC8  = mk(S8, -S8);
    const qtw TMC8 = mk(-S8, -S8);
    q64 s0 = qadd(v[0], v[4]), d0 = qsub(v[0], v[4], n1);
    q64 s1 = qadd(v[1], v[5]), d1 = qsub(v[1], v[5], n1);
    q64 s2 = qadd(v[2], v[6]), d2 = qsub(v[2], v[6], n1);
    q64 s3 = qadd(v[3], v[7]), d3 = qsub(v[3], v[7], n1);
    v[0] = s0; v[1] = s1; v[2] = s2; v[3] = s3;
    v[4] = d0;
    v[5] = qcmul(d1, TC8);
    v[6] = qmul(qswp(d2), p1m1);
    v[7] = qcmul(d3, TMC8);

    #pragma unroll
    for (int h = 0; h < 8; h += 4) {
        q64 u = qsub(v[h + 0], v[h + 2], n1);
        v[h + 0] = qadd(v[h + 0], v[h + 2]);
        v[h + 2] = u;
        u = qsub(v[h + 1], v[h + 3], n1);
        v[h + 1] = qadd(v[h + 1], v[h + 3]);
        v[h + 3] = qmul(qswp(u), p1m1);
    }
    #pragma unroll
    for (int h = 0; h < 8; h += 2) {
        const q64 u = qsub(v[h], v[h + 1], n1);
        v[h] = qadd(v[h], v[h + 1]);
        v[h + 1] = u;
    }
}

__device__ __forceinline__ void uinv8(q64 v[8], q64 n1, q64 m1p1) {
    #pragma unroll
    for (int h = 0; h < 8; h += 2) {
        const q64 t = v[h + 1];
        v[h + 1] = qsub(v[h], t, n1);
        v[h]     = qadd(v[h], t);
    }
    #pragma unroll
    for (int h = 0; h < 8; h += 4) {
        q64 t = v[h + 2];
        v[h + 2] = qsub(v[h], t, n1);
        v[h]     = qadd(v[h], t);
        t = qmul(qswp(v[h + 3]), m1p1);
        v[h + 3] = qsub(v[h + 1], t, n1);
        v[h + 1] = qadd(v[h + 1], t);
    }
    {
        const qtw TC1 = mk(S8, S8);
        const qtw TC3 = mk(-S8, S8);
        q64 t = v[4];
        v[4] = qsub(v[0], t, n1);
        v[0] = qadd(v[0], t);
        t = qcmul(v[5], TC1);
        v[5] = qsub(v[1], t, n1);
        v[1] = qadd(v[1], t);
        t = qmul(qswp(v[6]), m1p1);
        v[6] = qsub(v[2], t, n1);
        v[2] = qadd(v[2], t);
        t = qcmul(v[7], TC3);
        v[7] = qsub(v[3], t, n1);
        v[3] = qadd(v[3], t);
    }
}

// Reduced midpair: E' = 0.5*hm*(e^2 + w2c*o^2), O' = hm*e*o.
__device__ __forceinline__ void midpair2q(q64& zk, q64& zm, float2 w2c, float hm,
                                          q64 p1m1, q64 m1p1) {
    const q64 e = qfma(zm, p1m1, zk);
    const q64 o = qfma(qswp(zk), p1m1, qswp(zm));

    const float2 ef = qun(e), of = qun(o);
    const float2 t  = cadd(csq(ef), cmul(csq(of), w2c));
    const float hh  = 0.5f * hm;
    const float2 eo = cmul(ef, of);

    const q64 EP = qpk(hh * t.x, hh * t.y);
    const q64 OP = qpk(hm * eo.x, hm * eo.y);

    zk = qfma(qswp(OP), m1p1, EP);
    zm = qfma(EP, p1m1, qswp(OP));
}

__global__ void __launch_bounds__(NT, 1)
conv_self_rfft8m2_kernel(const float* __restrict__ x, float* __restrict__ out) {
    q64* z = s_z;

    const int tid = threadIdx.x;
    const int b   = blockIdx.x;
    const q64 n1   = qpk(-1.0f, -1.0f);
    const q64 p1m1 = qpk(1.0f, -1.0f);
    const q64 m1p1 = qpk(-1.0f, 1.0f);

    // ---- gmem loads FIRST (overlap DRAM latency with MUFU below) ----
    const q64* xb2 = (const q64*)(x + (size_t)b * SEQ_L);
    q64 g0 = xb2[tid], g1 = xb2[tid + 512], g2 = xb2[tid + 1024], g3 = xb2[tid + 1536];

    // ---- ALL pass twiddles via independent sincosf (MUFU; no serial chains)
    const int tb = (tid & 63) * 8;
    const int tc = (tid & 7) * 64;
    const float2 w1a = twof(tid),     w2a = twof(2 * tid), w4a = twof(4 * tid);
    const float2 w1b = twof(tb),      w2b = twof(2 * tb),  w4b = twof(4 * tb);
    const float2 w1c = twof(tc),      w2c = twof(2 * tc),  w4c = twof(4 * tc);

    // hoisted smem index arrays (shared by fwd/inv mirror passes)
    int ixb[8], ixc[8];
    {
        const int p2 = tid & 63;
        const int b2 = ((tid - p2) << 3) + p2;
        const int p3 = tid & 7;
        const int b3 = ((tid - p3) << 3) + p3;
        #pragma unroll
        for (int k = 0; k < 8; k++) {
            ixb[k] = IDX(b2 + k * 64);
            ixc[k] = IDX(b3 + k * 8);
        }
    }

    // ---- fwd pass1: len=4096; inputs in regs; upper half structural zero
    {
        q64 v[8];
        v[0] = g0; v[1] = g1; v[2] = g2; v[3] = g3;

        const qtw T1 = mk(w1a.x, w1a.y);
        const qtw TB = mk(S8 * (w1a.x + w1a.y), S8 * (w1a.y - w1a.x));
        const qtw TC = mk(w1a.y, -w1a.x);
        const qtw TD = mk(-S8 * (w1a.x - w1a.y), -S8 * (w1a.y + w1a.x));

        v[4] = qcmul(v[0], T1);
        v[5] = qcmul(v[1], TB);
        v[6] = qcmul(v[2], TC);
        v[7] = qcmul(v[3], TD);
        qfwd8_s23(v, w2a, w4a, n1);

        #pragma unroll
        for (int k = 0; k < 8; k++) z[IDX(tid + k * 512)] = v[k];
    }
    __syncthreads();

    // ---- fwd pass2: len=512 (64-thread groups)
    {
        q64 v[8];
        #pragma unroll
        for (int k = 0; k < 8; k++) v[k] = z[ixb[k]];
        qfwd8(v, w1b, w2b, w4b, n1);
        #pragma unroll
        for (int k = 0; k < 8; k++) z[ixb[k]] = v[k];
    }
    BAR_PAIR(tid);

    // ---- fwd pass3: len=64 (warp-contained)
    {
        q64 v[8];
        #pragma unroll
        for (int k = 0; k < 8; k++) v[k] = z[ixc[k]];
        qfwd8(v, w1c, w2c, w4c, n1);
        #pragma unroll
        for (int k = 0; k < 8; k++) z[ixc[k]] = v[k];
    }
    __syncthreads();

    // ---- Register-fused center (packed): fwd pass4 + reduced middle + inv passA
    if (tid < 256) {
        int oa, oc;
        if (tid == 0) { oa = 0; oc = 1; }
        else {
            const int msbu = 1 << (31 - __clz(tid));
            const int O = msbu << 1;
            oa = O + (tid - msbu);
            oc = 3 * O - 1 - oa;
        }

        q64 a[8], c[8];
        {
            const float4* pa = (const float4*)&z[IDX(8 * oa)];
            const float4* pc = (const float4*)&z[IDX(8 * oc)];
            #pragma unroll
            for (int i = 0; i < 4; i++) {
                const float4 va = pa[i], vc = pc[i];
                a[2 * i]     = qpk(va.x, va.y);
                a[2 * i + 1] = qpk(va.z, va.w);
                c[2 * i]     = qpk(vc.x, vc.y);
                c[2 * i + 1] = qpk(vc.z, vc.w);
            }
        }

        ufwd8(a, n1, p1m1);
        ufwd8(c, n1, p1m1);

        const float hm = 0.5f / (float)FFT_M;
        if (tid == 0) {
            {
                const float2 z0 = qun(a[0]);
                const float P = z0.x + z0.y, Q = z0.x - z0.y;
                a[0] = qpk(hm * (P * P + Q * Q), hm * (P * P - Q * Q));
                const float2 z1 = qun(a[1]);
                a[1] = qpk(2.0f * hm * (z1.x * z1.x - z1.y * z1.y),
                           4.0f * hm * (z1.x * z1.y));
            }
            midpair2q(a[2], a[3], make_float2(0.f, -1.f), hm, p1m1, m1p1);
            midpair2q(a[4], a[7], make_float2(S8, -S8), hm, p1m1, m1p1);
            midpair2q(a[5], a[6], make_float2(-S8, S8), hm, p1m1, m1p1);
            midpair2q(c[0], c[7], make_float2(C16, -S16), hm, p1m1, m1p1);
            midpair2q(c[1], c[6], make_float2(-C16, S16), hm, p1m1, m1p1);
            midpair2q(c[2], c[5], make_float2(-S16, -C16), hm, p1m1, m1p1);
            midpair2q(c[3], c[4], make_float2(S16, C16), hm, p1m1, m1p1);
        } else {
            const int k_base = __brev((unsigned)(8 * oa)) >> 20;
            const float2 wmb = twof(k_base);     // W_M^{k_base}
            const float2 W0 = wmb;
            const float2 W1 = make_float2(-wmb.x, -wmb.y);
            const float2 W2 = make_float2(wmb.y, -wmb.x);
            const float2 W3 = make_float2(-wmb.y, wmb.x);
            const float2 W4 = make_float2(S8 * (wmb.x + wmb.y), S8 * (wmb.y - wmb.x));
            const float2 W5 = make_float2(-W4.x, -W4.y);
            const float2 W6 = make_float2(S8 * (wmb.y - wmb.x), -S8 * (wmb.x + wmb.y));
            const float2 W7 = make_float2(-W6.x, -W6.y);
            midpair2q(a[0], c[7], W0, hm, p1m1, m1p1);
            midpair2q(a[1], c[6], W1, hm, p1m1, m1p1);
            midpair2q(a[2], c[5], W2, hm, p1m1, m1p1);
            midpair2q(a[3], c[4], W3, hm, p1m1, m1p1);
            midpair2q(a[4], c[3], W4, hm, p1m1, m1p1);
            midpair2q(a[5], c[2], W5, hm, p1m1, m1p1);
            midpair2q(a[6], c[1], W6, hm, p1m1, m1p1);
            midpair2q(a[7], c[0], W7, hm, p1m1, m1p1);
        }

        uinv8(a, n1, m1p1);
        uinv8(c, n1, m1p1);

        {
            float4* pa = (float4*)&z[IDX(8 * oa)];
            float4* pc = (float4*)&z[IDX(8 * oc)];
            #pragma unroll
            for (int i = 0; i < 4; i++) {
                const float2 a0 = qun(a[2 * i]), a1 = qun(a[2 * i + 1]);
                const float2 c0 = qun(c[2 * i]), c1 = qun(c[2 * i + 1]);
                pa[i] = make_float4(a0.x, a0.y, a1.x, a1.y);
                pc[i] = make_float4(c0.x, c0.y, c1.x, c1.y);
            }
        }
    }
    __syncthreads();

    // ---- inv passB: lenBig=64 (warp-contained)
    {
        q64 v[8];
        #pragma unroll
        for (int k = 0; k < 8; k++) v[k] = z[ixc[k]];
        qinv8(v, w1c, w2c, w4c, n1);
        #pragma unroll
        for (int k = 0; k < 8; k++) z[ixc[k]] = v[k];
    }
    BAR_PAIR(tid);

    // ---- inv passC: lenBig=512 (64-thread groups)
    {
        q64 v[8];
        #pragma unroll
        for (int k = 0; k < 8; k++) v[k] = z[ixb[k]];
        qinv8(v, w1b, w2b, w4b, n1);
        #pragma unroll
        for (int k = 0; k < 8; k++) z[ixb[k]] = v[k];
    }
    __syncthreads();

    // ---- inv passD: lenBig=4096, thread-local slots (tid + 512k)
    q64 v[8];
    {
        #pragma unroll
        for (int k = 0; k < 8; k++) v[k] = z[IDX(tid + k * 512)];
        qinv8(v, w1a, w2a, w4a, n1);
    }
    // no barrier: store reads this thread's registers

    // ---- Store (already scaled). Only tid=511,k=7 hits the 8191 edge.
    float* ob = out + (size_t)b * OUT_L;
    #pragma unroll
    for (int k = 0; k < 7; k++) {
        const int m = tid + k * 512;
        const float2 f = qun(v[k]);
        ob[2 * m]     = f.x;
        ob[2 * m + 1] = f.y;
    }
    {
        const int m = tid + 7 * 512;
        const float2 f = qun(v[7]);
        ob[2 * m] = f.x;
        if (tid != 511) ob[2 * m + 1] = f.y;
    }
}

extern "C" void kernel_launch(void* const* d_in, const int* in_sizes, int n_in,
                              void* d_out, int out_size) {
    (void)in_sizes; (void)n_in; (void)out_size;
    const float* x = (const float*)d_in[0];
    float* out = (float*)d_out;

    const int smem_bytes = RE_SZ * (int)sizeof(q64);  // 36 KB
    cudaFuncSetAttribute(conv_self_rfft8m2_kernel,
                         cudaFuncAttributeMaxDynamicSharedMemorySize, smem_bytes);

    conv_self_rfft8m2_kernel<<<128, NT, smem_bytes>>>(x, out);
}